// round 8
// baseline (speedup 1.0000x reference)
#include <cuda_runtime.h>
#include <math.h>

#define D_MODEL   1024
#define N_HEADS   16
#define HEAD_DIM  64
#define BATCH     2
#define TLEN      2048
#define WINDOW    128
#define MROWS     (BATCH * TLEN)      // 4096

// Scratch (allocation-free rule: __device__ globals; device-code access only)
__device__ float g_q[BATCH * N_HEADS * TLEN * HEAD_DIM];     // [b,h,t,d]
__device__ float g_k[BATCH * N_HEADS * TLEN * HEAD_DIM];
__device__ float g_v[BATCH * N_HEADS * TLEN * HEAD_DIM];
__device__ float g_attn[MROWS * D_MODEL];                    // [b*T+t, h*64+d]

// ---------------------------------------------------------------------------
// SGEMM: C[M,N] = A[M,K] @ W[N,K]^T   (K = D_MODEL = 1024)  [validated R5]
// ---------------------------------------------------------------------------
#define BM 128
#define BN 128
#define BKK 16

template <int MODE>
__global__ __launch_bounds__(256) void sgemm_kernel(
    const float* __restrict__ A_in, const float* __restrict__ W0,
    const float* __restrict__ W1, const float* __restrict__ W2,
    const float* __restrict__ bias, float* __restrict__ Cout)
{
    __shared__ float As[BKK][BM + 4];
    __shared__ float Bs[BKK][BN + 4];
    const int tid = threadIdx.x;
    const int m0 = blockIdx.y * BM;
    const int n0 = blockIdx.x * BN;
    const int K  = D_MODEL;

    const float* A = (MODE == 0) ? g_attn : A_in;
    const float* W = W0;
    float* dst = Cout;
    if (MODE == 1) {
        const int z = blockIdx.z;
        W   = (z == 0) ? W0 : (z == 1) ? W1 : W2;
        dst = (z == 0) ? g_q : (z == 1) ? g_k : g_v;
    }
    const int tx = tid & 15, ty = tid >> 4;

    float acc[8][8];
#pragma unroll
    for (int i = 0; i < 8; i++)
#pragma unroll
        for (int j = 0; j < 8; j++) acc[i][j] = 0.f;

    for (int k0 = 0; k0 < K; k0 += BKK) {
#pragma unroll
        for (int it = 0; it < 2; it++) {
            const int idx = tid + it * 256;
            const int row = idx >> 2;
            const int c   = (idx & 3) * 4;
            float4 va = *(const float4*)&A[(size_t)(m0 + row) * K + k0 + c];
            As[c + 0][row] = va.x; As[c + 1][row] = va.y;
            As[c + 2][row] = va.z; As[c + 3][row] = va.w;
            float4 vb = *(const float4*)&W[(size_t)(n0 + row) * K + k0 + c];
            Bs[c + 0][row] = vb.x; Bs[c + 1][row] = vb.y;
            Bs[c + 2][row] = vb.z; Bs[c + 3][row] = vb.w;
        }
        __syncthreads();
#pragma unroll
        for (int k = 0; k < BKK; k++) {
            float4 a0 = *(const float4*)&As[k][ty * 8];
            float4 a1 = *(const float4*)&As[k][ty * 8 + 4];
            float4 b0 = *(const float4*)&Bs[k][tx * 8];
            float4 b1 = *(const float4*)&Bs[k][tx * 8 + 4];
            float af[8] = {a0.x, a0.y, a0.z, a0.w, a1.x, a1.y, a1.z, a1.w};
            float bf[8] = {b0.x, b0.y, b0.z, b0.w, b1.x, b1.y, b1.z, b1.w};
#pragma unroll
            for (int i = 0; i < 8; i++)
#pragma unroll
                for (int j = 0; j < 8; j++)
                    acc[i][j] = fmaf(af[i], bf[j], acc[i][j]);
        }
        __syncthreads();
    }
#pragma unroll
    for (int i = 0; i < 8; i++) {
        const int m = m0 + ty * 8 + i;
#pragma unroll
        for (int j4 = 0; j4 < 8; j4 += 4) {
            const int n = n0 + tx * 8 + j4;
            float4 v;
            v.x = acc[i][j4 + 0]; v.y = acc[i][j4 + 1];
            v.z = acc[i][j4 + 2]; v.w = acc[i][j4 + 3];
            if (MODE == 0) {
                v.x += bias[n + 0]; v.y += bias[n + 1];
                v.z += bias[n + 2]; v.w += bias[n + 3];
                *(float4*)&dst[(size_t)m * D_MODEL + n] = v;
            } else {
                const int b = m >> 11, t = m & (TLEN - 1);
                const int h = n >> 6,  d = n & 63;
                const size_t o = ((((size_t)b * N_HEADS + h) * TLEN) + t) * HEAD_DIM + d;
                *(float4*)&dst[o] = v;
            }
        }
    }
}

// ---------------------------------------------------------------------------
// RoPE (half-split). FIXED: sincosf(x, &sin, &cos) — sin pointer FIRST.
// ---------------------------------------------------------------------------
__global__ __launch_bounds__(256) void rope_kernel()
{
    const int idx = blockIdx.x * blockDim.x + threadIdx.x;
    const int d  = idx & 31;
    const int t  = (idx >> 5) & (TLEN - 1);
    const int bh = idx >> 16;
    const size_t base = ((size_t)bh * TLEN + t) * HEAD_DIM;

    const float invf = expf((float)d * (-logf(10000.0f) / 32.0f));
    float s, c;
    sincosf((float)t * invf, &s, &c);    // <<< THE FIX: sin first, cos second
    {
        float x0 = g_q[base + d], x1 = g_q[base + d + 32];
        g_q[base + d]      = x0 * c - x1 * s;
        g_q[base + d + 32] = x1 * c + x0 * s;
    }
    {
        float x0 = g_k[base + d], x1 = g_k[base + d + 32];
        g_k[base + d]      = x0 * c - x1 * s;
        g_k[base + d + 32] = x1 * c + x0 * s;
    }
}

// ---------------------------------------------------------------------------
// Sliding-window attention (validated vs naive in R5). Block = (qtile 64,h,b),
// 256 threads / 8 warps. Full 192-row K/V window in smem; exact window
// enumeration j = qi-127+lane+32*c4 (j<=qi by construction, guard j>=0).
// ---------------------------------------------------------------------------
#define ATTN_SMEM ((64*64 + 192*68 + 192*64 + 8*128) * 4)   // 121856 B

__global__ __launch_bounds__(256) void attn_kernel()
{
    extern __shared__ float smx[];
    float* Qs = smx;                  // 64 x 64
    float* Ks = Qs + 64 * 64;         // 192 x 68 (padded)
    float* Vs = Ks + 192 * 68;        // 192 x 64
    float* Ps = Vs + 192 * 64;        // 8 x 128

    const int q0 = blockIdx.x * 64;
    const int h  = blockIdx.y;
    const int b  = blockIdx.z;
    const int tid  = threadIdx.x;
    const int w    = tid >> 5;
    const int lane = tid & 31;

    const size_t head_base = (((size_t)b * N_HEADS + h) * TLEN) * HEAD_DIM;
    const float* qb = g_q + head_base;
    const float* kb = g_k + head_base;
    const float* vb = g_v + head_base;

#pragma unroll
    for (int it = 0; it < 4; it++) {
        const int idx = tid + it * 256;
        const int r = idx >> 4, c = (idx & 15) * 4;
        *(float4*)&Qs[r * 64 + c] = *(const float4*)&qb[(size_t)(q0 + r) * 64 + c];
    }
#pragma unroll
    for (int it = 0; it < 12; it++) {
        const int idx = tid + it * 256;
        const int r = idx >> 4, c = (idx & 15) * 4;
        const int key = q0 - 128 + r;
        float4 kv = make_float4(0.f, 0.f, 0.f, 0.f);
        float4 vv = make_float4(0.f, 0.f, 0.f, 0.f);
        if (key >= 0) {
            kv = *(const float4*)&kb[(size_t)key * 64 + c];
            vv = *(const float4*)&vb[(size_t)key * 64 + c];
        }
        *(float4*)&Ks[r * 68 + c] = kv;
        *(float4*)&Vs[r * 64 + c] = vv;
    }
    __syncthreads();

    const float sm_scale = 0.125f;   // 1/sqrt(64)

    for (int r = 0; r < 8; r++) {
        const int qr = w * 8 + r;
        const int qi = q0 + qr;
        const int lb = qi - (WINDOW - 1);

        float4 qv[16];
        const float4* q4 = (const float4*)&Qs[qr * 64];
#pragma unroll
        for (int c = 0; c < 16; c++) qv[c] = q4[c];

        float s[4];
#pragma unroll
        for (int c4 = 0; c4 < 4; c4++) {
            const int j   = lb + lane + 32 * c4;
            const int row = j - (q0 - 128);
            const float4* k4 = (const float4*)&Ks[row * 68];
            float acc = 0.f;
#pragma unroll
            for (int c = 0; c < 16; c++) {
                float4 kk = k4[c];
                acc += qv[c].x * kk.x + qv[c].y * kk.y + qv[c].z * kk.z + qv[c].w * kk.w;
            }
            s[c4] = (j >= 0) ? acc * sm_scale : -INFINITY;
        }

        float mx = fmaxf(fmaxf(s[0], s[1]), fmaxf(s[2], s[3]));
#pragma unroll
        for (int o = 16; o > 0; o >>= 1)
            mx = fmaxf(mx, __shfl_xor_sync(0xffffffffu, mx, o));
        float l = 0.f;
#pragma unroll
        for (int c4 = 0; c4 < 4; c4++) { s[c4] = expf(s[c4] - mx); l += s[c4]; }
#pragma unroll
        for (int o = 16; o > 0; o >>= 1)
            l += __shfl_xor_sync(0xffffffffu, l, o);

#pragma unroll
        for (int c4 = 0; c4 < 4; c4++)
            Ps[w * 128 + lane + 32 * c4] = s[c4];
        __syncwarp();

        float a0 = 0.f, a1 = 0.f;
        const int row0 = qr + 1;
#pragma unroll 4
        for (int kk = 0; kk < WINDOW; kk++) {
            const float p = Ps[w * 128 + kk];
            a0 = fmaf(p, Vs[(row0 + kk) * 64 + lane],      a0);
            a1 = fmaf(p, Vs[(row0 + kk) * 64 + lane + 32], a1);
        }
        __syncwarp();

        const float inv = 1.0f / l;
        const size_t o = ((size_t)b * TLEN + qi) * D_MODEL + h * HEAD_DIM;
        g_attn[o + lane]      = a0 * inv;
        g_attn[o + lane + 32] = a1 * inv;
    }
}

// ---------------------------------------------------------------------------
extern "C" void kernel_launch(void* const* d_in, const int* in_sizes, int n_in,
                              void* d_out, int out_size)
{
    const float* query = (const float*)d_in[0];
    const float* Wq    = (const float*)d_in[1];
    const float* Wk    = (const float*)d_in[2];
    const float* Wv    = (const float*)d_in[3];
    const float* Wo    = (const float*)d_in[4];
    const float* bo    = (const float*)d_in[5];
    float* out = (float*)d_out;

    cudaFuncSetAttribute(attn_kernel,
                         cudaFuncAttributeMaxDynamicSharedMemorySize, ATTN_SMEM);

    // 1) QKV projections -> g_q/g_k/g_v in [b,h,t,d]
    sgemm_kernel<1><<<dim3(D_MODEL / BN, MROWS / BM, 3), 256>>>(
        query, Wq, Wk, Wv, nullptr, nullptr);

    // 2) RoPE in place (sincosf argument order FIXED)
    rope_kernel<<<(BATCH * N_HEADS * TLEN * 32) / 256, 256>>>();

    // 3) Sliding-window attention -> g_attn [b*T+t, D]
    attn_kernel<<<dim3(TLEN / 64, N_HEADS, BATCH), 256, ATTN_SMEM>>>();

    // 4) Output projection + bias -> d_out
    sgemm_kernel<0><<<dim3(D_MODEL / BN, MROWS / BM, 1), 256>>>(
        nullptr, Wo, nullptr, nullptr, bo, out);
}

// round 11
// speedup vs baseline: 2.7786x; 2.7786x over previous
#include <cuda_runtime.h>
#include <cuda_bf16.h>
#include <cstdint>
#include <math.h>

#define D_MODEL   1024
#define N_HEADS   16
#define HEAD_DIM  64
#define BATCH     2
#define TLEN      2048
#define WINDOW    128
#define MROWS     (BATCH * TLEN)          // 4096
#define QKV_N     (MROWS * D_MODEL)       // 4194304

// fp32 scratch
__device__ float g_q[QKV_N];
__device__ float g_k[QKV_N];
__device__ float g_v[QKV_N];
__device__ float g_attn[QKV_N];
// bf16 split scratch
__device__ __nv_bfloat16 g_qh[QKV_N], g_ql[QKV_N];
__device__ __nv_bfloat16 g_wh[4][D_MODEL * D_MODEL];
__device__ __nv_bfloat16 g_wl[4][D_MODEL * D_MODEL];
__device__ __nv_bfloat16 g_ah[QKV_N], g_al[QKV_N];

// ---------------------------------------------------------------------------
__device__ __forceinline__ uint32_t smem_u32(const void* p) {
    uint32_t a;
    asm("{ .reg .u64 t; cvta.to.shared.u64 t, %1; cvt.u32.u64 %0, t; }"
        : "=r"(a) : "l"(p));
    return a;
}

#define CP_ASYNC16(dst, src) \
    asm volatile("cp.async.cg.shared.global [%0], [%1], 16;" :: "r"(dst), "l"(src))
#define CP_COMMIT()  asm volatile("cp.async.commit_group;" ::: "memory")
#define CP_WAIT(n)   asm volatile("cp.async.wait_group %0;" :: "n"(n) : "memory")

#define LDSM4(r0, r1, r2, r3, a) \
    asm volatile("ldmatrix.sync.aligned.m8n8.x4.shared.b16 {%0,%1,%2,%3}, [%4];" \
                 : "=r"(r0), "=r"(r1), "=r"(r2), "=r"(r3) : "r"(a))

__device__ __forceinline__ void mma_bf16(float* d, uint32_t a0, uint32_t a1,
                                         uint32_t a2, uint32_t a3,
                                         uint32_t b0, uint32_t b1) {
    asm volatile(
        "mma.sync.aligned.m16n8k16.row.col.f32.bf16.bf16.f32 "
        "{%0,%1,%2,%3}, {%4,%5,%6,%7}, {%8,%9}, {%0,%1,%2,%3};"
        : "+f"(d[0]), "+f"(d[1]), "+f"(d[2]), "+f"(d[3])
        : "r"(a0), "r"(a1), "r"(a2), "r"(a3), "r"(b0), "r"(b1));
}

// ---------------------------------------------------------------------------
// fp32 -> (bf16 hi, bf16 lo) split
// ---------------------------------------------------------------------------
template <int DST>
__global__ __launch_bounds__(256) void split_kernel(const float* __restrict__ src_in, int n4)
{
    const float* src = (DST == 5) ? g_attn : src_in;
    __nv_bfloat16 *dh, *dl;
    if (DST == 0)      { dh = g_qh; dl = g_ql; }
    else if (DST == 5) { dh = g_ah; dl = g_al; }
    else               { dh = g_wh[DST - 1]; dl = g_wl[DST - 1]; }

    const int i = blockIdx.x * 256 + threadIdx.x;
    if (i >= n4) return;
    float4 x = ((const float4*)src)[i];
    __nv_bfloat16 h0 = __float2bfloat16(x.x), h1 = __float2bfloat16(x.y);
    __nv_bfloat16 h2 = __float2bfloat16(x.z), h3 = __float2bfloat16(x.w);
    __nv_bfloat16 l0 = __float2bfloat16(x.x - __bfloat162float(h0));
    __nv_bfloat16 l1 = __float2bfloat16(x.y - __bfloat162float(h1));
    __nv_bfloat16 l2 = __float2bfloat16(x.z - __bfloat162float(h2));
    __nv_bfloat16 l3 = __float2bfloat16(x.w - __bfloat162float(h3));
    uint2 uh, ul;
    uh.x = (uint32_t)__bfloat16_as_ushort(h0) | ((uint32_t)__bfloat16_as_ushort(h1) << 16);
    uh.y = (uint32_t)__bfloat16_as_ushort(h2) | ((uint32_t)__bfloat16_as_ushort(h3) << 16);
    ul.x = (uint32_t)__bfloat16_as_ushort(l0) | ((uint32_t)__bfloat16_as_ushort(l1) << 16);
    ul.y = (uint32_t)__bfloat16_as_ushort(l2) | ((uint32_t)__bfloat16_as_ushort(l3) << 16);
    ((uint2*)dh)[i] = uh;
    ((uint2*)dl)[i] = ul;
}

// ---------------------------------------------------------------------------
// bf16 mma.sync split GEMM: C[M,N] = A[M,K] @ W[N,K]^T, K=1024.
// CTA 128x128, 8 warps (4M x 2N), warp tile 32x64, BK=32,
// cp.async double-buffered, row pitch 40 bf16 (80B -> conflict-free ldmatrix).
// MODE 1: A=query splits, z selects W, dst=g_q/g_k/g_v, RoPE fused (z<2).
// MODE 0: A=attn splits, W=Wo, +bias, row-major out.
// ---------------------------------------------------------------------------
#define PITCH   40                       // bf16 per row (80 bytes)
#define MATSZ   (128 * PITCH)            // 5120 bf16 per matrix
#define STAGEB  (4 * MATSZ * 2)          // 40960 bytes per stage
#define GSMEM   (2 * STAGEB)             // 81920

template <int MODE>
__global__ __launch_bounds__(256, 1) void tc_gemm(const float* __restrict__ bias,
                                                  float* __restrict__ Cout)
{
    extern __shared__ __nv_bfloat16 sm[];
    const uint32_t sb = smem_u32(sm);
    const int tid  = threadIdx.x;
    const int lane = tid & 31, warp = tid >> 5;
    const int z    = (MODE == 1) ? blockIdx.z : 3;
    const int m0   = blockIdx.y * 128;
    const int n0   = blockIdx.x * 128;
    const int wm   = (warp >> 1) * 32;
    const int wn   = (warp & 1) * 64;

    const __nv_bfloat16* Ah = (MODE == 1) ? g_qh : g_ah;
    const __nv_bfloat16* Al = (MODE == 1) ? g_ql : g_al;
    const __nv_bfloat16* Wh = g_wh[z];
    const __nv_bfloat16* Wl = g_wl[z];
    const __nv_bfloat16* mats[4] = {Ah, Al, Wh, Wl};

    float acc[2][8][4];
#pragma unroll
    for (int mi = 0; mi < 2; mi++)
#pragma unroll
        for (int ni = 0; ni < 8; ni++)
#pragma unroll
            for (int e = 0; e < 4; e++) acc[mi][ni][e] = 0.f;

    // ---- async load of one stage ----
    auto load_stage = [&](int buf, int k0) {
#pragma unroll
        for (int it = 0; it < 8; it++) {
            const int i   = tid + it * 256;      // 0..2047
            const int mat = i >> 9;
            const int r   = (i >> 2) & 127;
            const int c4  = i & 3;
            const uint32_t dst = sb + buf * STAGEB +
                                 (mat * MATSZ + r * PITCH + c4 * 8) * 2;
            const int grow = (mat < 2) ? (m0 + r) : (n0 + r);
            const __nv_bfloat16* src = mats[mat] + (size_t)grow * D_MODEL + k0 + c4 * 8;
            CP_ASYNC16(dst, src);
        }
        CP_COMMIT();
    };

    load_stage(0, 0);

    for (int ch = 0; ch < 32; ch++) {
        const int buf = ch & 1;
        if (ch + 1 < 32) load_stage(buf ^ 1, (ch + 1) * 32);
        if (ch + 1 < 32) CP_WAIT(1); else CP_WAIT(0);
        __syncthreads();

        const uint32_t base = sb + buf * STAGEB;
#pragma unroll
        for (int ks = 0; ks < 2; ks++) {
            const int kk = ks * 16;
            // A fragments (hi, lo) for mi = 0,1
            uint32_t ah[2][4], al[2][4];
#pragma unroll
            for (int mi = 0; mi < 2; mi++) {
                const uint32_t ra = (uint32_t)((wm + mi * 16 + (lane & 15)) * PITCH
                                    + kk + ((lane >> 4) << 3)) * 2;
                LDSM4(ah[mi][0], ah[mi][1], ah[mi][2], ah[mi][3], base + 0 * MATSZ * 2 + ra);
                LDSM4(al[mi][0], al[mi][1], al[mi][2], al[mi][3], base + 1 * MATSZ * 2 + ra);
            }
            // B fragments (8 n-frags, hi+lo), two frags per x4 load
            uint32_t bh[8][2], bl[8][2];
#pragma unroll
            for (int ng = 0; ng < 8; ng += 2) {
                const uint32_t rb = (uint32_t)((wn + ng * 8 + (lane & 7) + ((lane >> 4) << 3)) * PITCH
                                    + kk + (((lane >> 3) & 1) << 3)) * 2;
                LDSM4(bh[ng][0], bh[ng][1], bh[ng + 1][0], bh[ng + 1][1],
                      base + 2 * MATSZ * 2 + rb);
                LDSM4(bl[ng][0], bl[ng][1], bl[ng + 1][0], bl[ng + 1][1],
                      base + 3 * MATSZ * 2 + rb);
            }
#pragma unroll
            for (int mi = 0; mi < 2; mi++)
#pragma unroll
                for (int ni = 0; ni < 8; ni++) {
                    mma_bf16(acc[mi][ni], ah[mi][0], ah[mi][1], ah[mi][2], ah[mi][3],
                             bh[ni][0], bh[ni][1]);
                    mma_bf16(acc[mi][ni], ah[mi][0], ah[mi][1], ah[mi][2], ah[mi][3],
                             bl[ni][0], bl[ni][1]);
                    mma_bf16(acc[mi][ni], al[mi][0], al[mi][1], al[mi][2], al[mi][3],
                             bh[ni][0], bh[ni][1]);
                }
        }
        __syncthreads();
    }

    // ---- epilogue ----
    const float coef = -logf(10000.0f) / 32.0f;
#pragma unroll
    for (int mi = 0; mi < 2; mi++) {
#pragma unroll
        for (int r8 = 0; r8 < 2; r8++) {
            const int m = m0 + wm + mi * 16 + (lane >> 2) + r8 * 8;
            const int t = m & (TLEN - 1);
            const int b = m >> 11;

            if (MODE == 1) {
                if (z < 2) {
#pragma unroll
                    for (int ni = 0; ni < 4; ni++)
#pragma unroll
                        for (int e = 0; e < 2; e++) {
                            const int dd = ni * 8 + ((lane & 3) << 1) + e;
                            float sn, cs;
                            sincosf((float)t * expf((float)dd * coef), &sn, &cs);
                            const float x0 = acc[mi][ni][r8 * 2 + e];
                            const float x1 = acc[mi][ni + 4][r8 * 2 + e];
                            acc[mi][ni][r8 * 2 + e]     = x0 * cs - x1 * sn;
                            acc[mi][ni + 4][r8 * 2 + e] = x1 * cs + x0 * sn;
                        }
                }
                float* dst = (z == 0) ? g_q : (z == 1) ? g_k : g_v;
                const int h = blockIdx.x * 2 + (warp & 1);
                const size_t off = (((size_t)b * N_HEADS + h) * TLEN + t) * HEAD_DIM;
#pragma unroll
                for (int ni = 0; ni < 8; ni++) {
                    const int d0 = ni * 8 + ((lane & 3) << 1);
                    *(float2*)&dst[off + d0] =
                        make_float2(acc[mi][ni][r8 * 2], acc[mi][ni][r8 * 2 + 1]);
                }
            } else {
                const size_t off = (size_t)m * D_MODEL + n0 + wn;
#pragma unroll
                for (int ni = 0; ni < 8; ni++) {
                    const int d0 = ni * 8 + ((lane & 3) << 1);
                    *(float2*)&Cout[off + d0] =
                        make_float2(acc[mi][ni][r8 * 2]     + __ldg(&bias[n0 + wn + d0]),
                                    acc[mi][ni][r8 * 2 + 1] + __ldg(&bias[n0 + wn + d0 + 1]));
                }
            }
        }
    }
}

// ---------------------------------------------------------------------------
// Sliding-window attention (validated R5/R8). Reads rotated g_q/g_k, g_v.
// ---------------------------------------------------------------------------
#define ATTN_SMEM ((64*64 + 192*68 + 192*64 + 8*128) * 4)

__global__ __launch_bounds__(256) void attn_kernel()
{
    extern __shared__ float smx[];
    float* Qs = smx;
    float* Ks = Qs + 64 * 64;
    float* Vs = Ks + 192 * 68;
    float* Ps = Vs + 192 * 64;

    const int q0 = blockIdx.x * 64;
    const int h  = blockIdx.y;
    const int b  = blockIdx.z;
    const int tid  = threadIdx.x;
    const int w    = tid >> 5;
    const int lane = tid & 31;

    const size_t head_base = (((size_t)b * N_HEADS + h) * TLEN) * HEAD_DIM;
    const float* qb = g_q + head_base;
    const float* kb = g_k + head_base;
    const float* vb = g_v + head_base;

#pragma unroll
    for (int it = 0; it < 4; it++) {
        const int idx = tid + it * 256;
        const int r = idx >> 4, c = (idx & 15) * 4;
        *(float4*)&Qs[r * 64 + c] = *(const float4*)&qb[(size_t)(q0 + r) * 64 + c];
    }
#pragma unroll
    for (int it = 0; it < 12; it++) {
        const int idx = tid + it * 256;
        const int r = idx >> 4, c = (idx & 15) * 4;
        const int key = q0 - 128 + r;
        float4 kv = make_float4(0.f, 0.f, 0.f, 0.f);
        float4 vv = make_float4(0.f, 0.f, 0.f, 0.f);
        if (key >= 0) {
            kv = *(const float4*)&kb[(size_t)key * 64 + c];
            vv = *(const float4*)&vb[(size_t)key * 64 + c];
        }
        *(float4*)&Ks[r * 68 + c] = kv;
        *(float4*)&Vs[r * 64 + c] = vv;
    }
    __syncthreads();

    const float sm_scale = 0.125f;
    for (int r = 0; r < 8; r++) {
        const int qr = w * 8 + r;
        const int qi = q0 + qr;
        const int lb = qi - (WINDOW - 1);

        float4 qv[16];
        const float4* q4 = (const float4*)&Qs[qr * 64];
#pragma unroll
        for (int c = 0; c < 16; c++) qv[c] = q4[c];

        float s[4];
#pragma unroll
        for (int c4 = 0; c4 < 4; c4++) {
            const int j   = lb + lane + 32 * c4;
            const int row = j - (q0 - 128);
            const float4* k4 = (const float4*)&Ks[row * 68];
            float acc = 0.f;
#pragma unroll
            for (int c = 0; c < 16; c++) {
                float4 kk = k4[c];
                acc += qv[c].x * kk.x + qv[c].y * kk.y + qv[c].z * kk.z + qv[c].w * kk.w;
            }
            s[c4] = (j >= 0) ? acc * sm_scale : -INFINITY;
        }

        float mx = fmaxf(fmaxf(s[0], s[1]), fmaxf(s[2], s[3]));
#pragma unroll
        for (int o = 16; o > 0; o >>= 1)
            mx = fmaxf(mx, __shfl_xor_sync(0xffffffffu, mx, o));
        float lsum = 0.f;
#pragma unroll
        for (int c4 = 0; c4 < 4; c4++) { s[c4] = expf(s[c4] - mx); lsum += s[c4]; }
#pragma unroll
        for (int o = 16; o > 0; o >>= 1)
            lsum += __shfl_xor_sync(0xffffffffu, lsum, o);

#pragma unroll
        for (int c4 = 0; c4 < 4; c4++)
            Ps[w * 128 + lane + 32 * c4] = s[c4];
        __syncwarp();

        float a0 = 0.f, a1 = 0.f;
        const int row0 = qr + 1;
#pragma unroll 4
        for (int kk = 0; kk < WINDOW; kk++) {
            const float p = Ps[w * 128 + kk];
            a0 = fmaf(p, Vs[(row0 + kk) * 64 + lane],      a0);
            a1 = fmaf(p, Vs[(row0 + kk) * 64 + lane + 32], a1);
        }
        __syncwarp();

        const float inv = 1.0f / lsum;
        const size_t o = ((size_t)b * TLEN + qi) * D_MODEL + h * HEAD_DIM;
        g_attn[o + lane]      = a0 * inv;
        g_attn[o + lane + 32] = a1 * inv;
    }
}

// ---------------------------------------------------------------------------
extern "C" void kernel_launch(void* const* d_in, const int* in_sizes, int n_in,
                              void* d_out, int out_size)
{
    const float* query = (const float*)d_in[0];
    const float* Wq    = (const float*)d_in[1];
    const float* Wk    = (const float*)d_in[2];
    const float* Wv    = (const float*)d_in[3];
    const float* Wo    = (const float*)d_in[4];
    const float* bo    = (const float*)d_in[5];
    float* out = (float*)d_out;

    cudaFuncSetAttribute(attn_kernel,
                         cudaFuncAttributeMaxDynamicSharedMemorySize, ATTN_SMEM);
    cudaFuncSetAttribute(tc_gemm<1>,
                         cudaFuncAttributeMaxDynamicSharedMemorySize, GSMEM);
    cudaFuncSetAttribute(tc_gemm<0>,
                         cudaFuncAttributeMaxDynamicSharedMemorySize, GSMEM);

    const int nq4 = QKV_N / 4, nw4 = (D_MODEL * D_MODEL) / 4;

    // 1) split inputs into bf16 hi/lo
    split_kernel<0><<<nq4 / 256, 256>>>(query, nq4);
    split_kernel<1><<<nw4 / 256, 256>>>(Wq, nw4);
    split_kernel<2><<<nw4 / 256, 256>>>(Wk, nw4);
    split_kernel<3><<<nw4 / 256, 256>>>(Wv, nw4);
    split_kernel<4><<<nw4 / 256, 256>>>(Wo, nw4);

    // 2) QKV projections via mma.sync (+fused RoPE for q,k)
    tc_gemm<1><<<dim3(D_MODEL / 128, MROWS / 128, 3), 256, GSMEM>>>(nullptr, nullptr);

    // 3) sliding-window attention
    attn_kernel<<<dim3(TLEN / 64, N_HEADS, BATCH), 256, ATTN_SMEM>>>();

    // 4) split attention output, then output projection (+bias)
    split_kernel<5><<<nq4 / 256, 256>>>(nullptr, nq4);
    tc_gemm<0><<<dim3(D_MODEL / 128, MROWS / 128, 1), 256, GSMEM>>>(bo, out);
}